// round 2
// baseline (speedup 1.0000x reference)
#include <cuda_runtime.h>
#include <cstdint>

// CharBiLSTMEmbedder: N=32768 words, T=20 chars, E=H=50, V=200, out [N, 2H] fp32.
//
// Strategy:
//  - Precompute xw[dir][v][cell*4+gate] = b_ih+b_hh + emb'[v] @ W_ih.T   (V=200 table,
//    kills the entire input-projection GEMM; emb row 0 zeroed per padding_idx).
//  - Precompute W_hh transposed+gate-interleaved: wt[dir][k][cell*4+gate].
//  - Main kernel: CTA = 128 words x 1 direction, 320 threads (tile 4 words x 5 cells).
//    xw table + W_hh^T + h state in smem (~231KB). c-state in registers.
//    Recurrent GEMM uses packed fma.rn.f32x2 (2 FMA/instr) -> 128 FMA/cyc/SM.

#define TT 20
#define HH 50
#define EE 50
#define VV 200
#define G4 200          // 4*H
#define NWORDS 128      // words per CTA
#define NTH 320         // threads per CTA (10 warps); warp = 32 word-groups, 1 cell-group
#define XWS 204         // padded xw row stride (floats); 204/4=51 16B-units, coprime w/ 8

// scratch tables (device globals: no allocation allowed)
__device__ float g_xw[2 * VV * G4];   // [dir][v][j*4+gi]
__device__ float g_wt[2 * HH * G4];   // [dir][k][j*4+gi]

// ---------- fast math helpers ----------
__device__ __forceinline__ float fast_ex2(float x) {
    float y; asm("ex2.approx.f32 %0, %1;" : "=f"(y) : "f"(x)); return y;
}
__device__ __forceinline__ float fast_rcp(float x) {
    float y; asm("rcp.approx.f32 %0, %1;" : "=f"(y) : "f"(x)); return y;
}
__device__ __forceinline__ float sigf(float x) {
    // 1/(1+2^(-x*log2e))
    return fast_rcp(1.0f + fast_ex2(-1.4426950408889634f * x));
}
__device__ __forceinline__ float tanhf_(float x) {
    // 2*sigmoid(2x)-1
    return 2.0f * fast_rcp(1.0f + fast_ex2(-2.8853900817779268f * x)) - 1.0f;
}
// packed f32x2 FMA (sm_100+): d = a*b + c on both lanes
__device__ __forceinline__ float2 ffma2(float2 a, float2 b, float2 c) {
    float2 d;
    asm("fma.rn.f32x2 %0, %1, %2, %3;"
        : "=l"(*reinterpret_cast<unsigned long long*>(&d))
        : "l"(*reinterpret_cast<unsigned long long*>(&a)),
          "l"(*reinterpret_cast<unsigned long long*>(&b)),
          "l"(*reinterpret_cast<unsigned long long*>(&c)));
    return d;
}
__device__ __forceinline__ float2 sp(float x) { return make_float2(x, x); }

// ---------- table builders ----------
__global__ void build_xw_kernel(const float* __restrict__ emb,
                                const float* __restrict__ Wih_f, const float* __restrict__ bih_f,
                                const float* __restrict__ bhh_f,
                                const float* __restrict__ Wih_b, const float* __restrict__ bih_b,
                                const float* __restrict__ bhh_b) {
    int idx = blockIdx.x * blockDim.x + threadIdx.x;
    if (idx >= 2 * VV * HH) return;
    int dir = idx / (VV * HH);
    int r   = idx % (VV * HH);
    int v   = r / HH;
    int j   = r % HH;
    const float* Wih = dir ? Wih_b : Wih_f;
    const float* bih = dir ? bih_b : bih_f;
    const float* bhh = dir ? bhh_b : bhh_f;
#pragma unroll
    for (int gi = 0; gi < 4; ++gi) {
        int g = gi * HH + j;
        float s = bih[g] + bhh[g];
        if (v != 0) {  // padding_idx = 0 -> embedding row zeroed
            const float* er = emb + v * EE;
            const float* wr = Wih + g * EE;
            float a = 0.f;
#pragma unroll
            for (int e = 0; e < EE; ++e) a += er[e] * wr[e];
            s += a;
        }
        g_xw[dir * VV * G4 + v * G4 + j * 4 + gi] = s;
    }
}

__global__ void build_wt_kernel(const float* __restrict__ Whh_f,
                                const float* __restrict__ Whh_b) {
    int idx = blockIdx.x * blockDim.x + threadIdx.x;
    if (idx >= 2 * HH * HH) return;
    int dir = idx / (HH * HH);
    int r   = idx % (HH * HH);
    int k   = r / HH;
    int j   = r % HH;
    const float* Whh = dir ? Whh_b : Whh_f;
#pragma unroll
    for (int gi = 0; gi < 4; ++gi)
        g_wt[dir * HH * G4 + k * G4 + j * 4 + gi] = Whh[(gi * HH + j) * HH + k];
}

// ---------- main LSTM kernel ----------
// grid: (ceil(N/128), 2)   block: 320
// smem layout (floats): sXW[200*204] | sW[50*200] | sH[50*128] | sCh u8[20*128]
#define SMEM_BYTES ((VV * XWS + HH * G4 + HH * NWORDS) * 4 + TT * NWORDS)

__global__ void __launch_bounds__(NTH, 1)
lstm_main_kernel(const int* __restrict__ chars, const int* __restrict__ lens,
                 float* __restrict__ out, int N) {
    extern __shared__ float smem[];
    float* sXW = smem;                        // VV * XWS
    float* sW  = sXW + VV * XWS;              // HH * G4
    float* sH  = sW + HH * G4;                // HH * NWORDS  (h[k][word])
    unsigned char* sCh = (unsigned char*)(sH + HH * NWORDS);  // [t][word]

    const int tid   = threadIdx.x;
    const int dir   = blockIdx.y;
    const int wbase = blockIdx.x * NWORDS;

    // stage tables (L2 -> smem), coalesced
    const float* gxw = g_xw + dir * VV * G4;
    for (int i = tid; i < VV * G4; i += NTH) {
        int v = i / G4, j = i % G4;
        sXW[v * XWS + j] = gxw[i];
    }
    const float* gwt = g_wt + dir * HH * G4;
    for (int i = tid; i < HH * G4; i += NTH) sW[i] = gwt[i];
    for (int i = tid; i < HH * NWORDS; i += NTH) sH[i] = 0.0f;
    for (int i = tid; i < NWORDS * TT; i += NTH) {
        int w = i / TT, t = i % TT;
        int word = wbase + w;
        int ch = (word < N) ? chars[word * TT + t] : 0;
        sCh[t * NWORDS + w] = (unsigned char)ch;
    }

    // thread tile: wg = word-group (4 words), cg = cell-group (5 cells)
    const int wg = tid & 31;        // 0..31 -> words wg*4 .. wg*4+3
    const int cg = tid >> 5;        // 0..9  -> cells cg*5 .. cg*5+4
    const int w0 = wg * 4;
    const int c0 = cg * 5;

    int lenr[4];
#pragma unroll
    for (int j = 0; j < 4; ++j) {
        int word = wbase + w0 + j;
        lenr[j] = (word < N) ? lens[word] : 0;
    }

    __syncthreads();

    float2 cst[2][5];               // c-state: pairs (w0,w1),(w2,w3) x 5 cells
#pragma unroll
    for (int p = 0; p < 2; ++p)
#pragma unroll
        for (int c = 0; c < 5; ++c) cst[p][c] = make_float2(0.f, 0.f);

    for (int s = 0; s < TT; ++s) {
        const int te = dir ? (TT - 1 - s) : s;

        // chars of my 4 words (one packed u32)
        unsigned pk = *(const unsigned*)(sCh + te * NWORDS + w0);
        int chv[4] = { (int)(pk & 255u), (int)((pk >> 8) & 255u),
                       (int)((pk >> 16) & 255u), (int)((pk >> 24) & 255u) };

        // init accumulators with xw[char] (gate-interleaved quads per cell)
        float2 acc[2][5][4];
#pragma unroll
        for (int p = 0; p < 2; ++p) {
            const float4* xa = (const float4*)(sXW + chv[2 * p] * XWS + c0 * 4);
            const float4* xb = (const float4*)(sXW + chv[2 * p + 1] * XWS + c0 * 4);
#pragma unroll
            for (int c = 0; c < 5; ++c) {
                float4 A = xa[c], B = xb[c];
                acc[p][c][0] = make_float2(A.x, B.x);
                acc[p][c][1] = make_float2(A.y, B.y);
                acc[p][c][2] = make_float2(A.z, B.z);
                acc[p][c][3] = make_float2(A.w, B.w);
            }
        }

        // recurrent GEMM: acc += h @ W_hh^T   (k-loop, 40 FFMA2 per k)
#pragma unroll 5
        for (int k = 0; k < HH; ++k) {
            float4 hv = *(const float4*)(sH + k * NWORDS + w0);
            float2 h01 = make_float2(hv.x, hv.y);
            float2 h23 = make_float2(hv.z, hv.w);
            const float4* wr = (const float4*)(sW + k * G4 + c0 * 4);
#pragma unroll
            for (int c = 0; c < 5; ++c) {
                float4 wv = wr[c];
                acc[0][c][0] = ffma2(h01, sp(wv.x), acc[0][c][0]);
                acc[1][c][0] = ffma2(h23, sp(wv.x), acc[1][c][0]);
                acc[0][c][1] = ffma2(h01, sp(wv.y), acc[0][c][1]);
                acc[1][c][1] = ffma2(h23, sp(wv.y), acc[1][c][1]);
                acc[0][c][2] = ffma2(h01, sp(wv.z), acc[0][c][2]);
                acc[1][c][2] = ffma2(h23, sp(wv.z), acc[1][c][2]);
                acc[0][c][3] = ffma2(h01, sp(wv.w), acc[0][c][3]);
                acc[1][c][3] = ffma2(h23, sp(wv.w), acc[1][c][3]);
            }
        }

        // grab old h for my (cells, words) before anyone overwrites
        float4 holdv[5];
#pragma unroll
        for (int c = 0; c < 5; ++c)
            holdv[c] = *(const float4*)(sH + (c0 + c) * NWORDS + w0);

        __syncthreads();  // all reads of sH done

        // epilogue: gates -> new c (regs) / new h (smem), masked by word length
#pragma unroll
        for (int c = 0; c < 5; ++c) {
            float hs[4];
            const float* hop = (const float*)&holdv[c];
#pragma unroll
            for (int j = 0; j < 4; ++j) {
                const int p = j >> 1;
                float xi, xf, xg, xo, cold;
                if (j & 1) {
                    xi = acc[p][c][0].y; xf = acc[p][c][1].y;
                    xg = acc[p][c][2].y; xo = acc[p][c][3].y;
                    cold = cst[p][c].y;
                } else {
                    xi = acc[p][c][0].x; xf = acc[p][c][1].x;
                    xg = acc[p][c][2].x; xo = acc[p][c][3].x;
                    cold = cst[p][c].x;
                }
                float cn = sigf(xf) * cold + sigf(xi) * tanhf_(xg);
                float hn = sigf(xo) * tanhf_(cn);
                bool valid = (te < lenr[j]);
                float cstore = valid ? cn : cold;
                if (j & 1) cst[p][c].y = cstore; else cst[p][c].x = cstore;
                hs[j] = valid ? hn : hop[j];
            }
            *(float4*)(sH + (c0 + c) * NWORDS + w0) = make_float4(hs[0], hs[1], hs[2], hs[3]);
        }

        __syncthreads();  // sH updated for next step
    }

    // write final h: out[word][dir*50 + k]
    for (int i = tid; i < HH * NWORDS; i += NTH) {
        int k = i / NWORDS, w = i % NWORDS;
        int word = wbase + w;
        if (word < N) out[word * (2 * HH) + dir * HH + k] = sH[k * NWORDS + w];
    }
}

// ---------- launcher ----------
extern "C" void kernel_launch(void* const* d_in, const int* in_sizes, int n_in,
                              void* d_out, int out_size) {
    const int*   chars = (const int*)d_in[0];
    const int*   lens  = (const int*)d_in[1];
    const float* emb   = (const float*)d_in[2];
    const float* Wih_f = (const float*)d_in[3];
    const float* Whh_f = (const float*)d_in[4];
    const float* bih_f = (const float*)d_in[5];
    const float* bhh_f = (const float*)d_in[6];
    const float* Wih_b = (const float*)d_in[7];
    const float* Whh_b = (const float*)d_in[8];
    const float* bih_b = (const float*)d_in[9];
    const float* bhh_b = (const float*)d_in[10];
    float* out = (float*)d_out;

    const int N = in_sizes[1];  // word_lengths element count

    {
        int total = 2 * VV * HH;
        build_xw_kernel<<<(total + 127) / 128, 128>>>(emb, Wih_f, bih_f, bhh_f,
                                                      Wih_b, bih_b, bhh_b);
    }
    {
        int total = 2 * HH * HH;
        build_wt_kernel<<<(total + 127) / 128, 128>>>(Whh_f, Whh_b);
    }

    cudaFuncSetAttribute(lstm_main_kernel,
                         cudaFuncAttributeMaxDynamicSharedMemorySize, SMEM_BYTES);
    dim3 grid((N + NWORDS - 1) / NWORDS, 2);
    lstm_main_kernel<<<grid, NTH, SMEM_BYTES>>>(chars, lens, out, N);
}

// round 4
// speedup vs baseline: 2.1304x; 2.1304x over previous
#include <cuda_runtime.h>
#include <cstdint>

// CharBiLSTMEmbedder: N=32768, T=20, E=H=50, V=200, out [N,2H] fp32.
//
// Round-4 design (tcgen05 unavailable: harness emits compute_103 base-target PTX):
//  - xw table: xw[dir][v][cell*4+gate] = b_ih+b_hh + emb'[v]@W_ih.T (kills input GEMM)
//  - counting-sort words by length DESCENDING -> CTA = 128 similar-length words;
//    loop only to block max length. Both directions need exactly len steps
//    (backward = forward over reversed prefix via per-word char index len-1-s).
//    Total CTA-steps: 10240 -> ~5140, no wave tail (LPT order).
//  - FFMA2 (fma.rn.f32x2) recurrent GEMM, tanh.approx gates (5 MUFU/cell),
//    thread-level skip when all 4 owned words are done.

#define TT 20
#define HH 50
#define EE 50
#define VV 200
#define G4 200
#define NW 128
#define NTH 320
#define XWS 204
#define NMAX 65536

__device__ float g_xw[2 * VV * G4];   // [dir][v][cell*4+gate]
__device__ float g_wt[2 * HH * G4];   // [dir][k][cell*4+gate]
__device__ int   g_cnt[32];
__device__ int   g_pos[32];
__device__ int   g_perm[NMAX];

// ---------- helpers ----------
__device__ __forceinline__ float tanha(float x) {
    float y; asm("tanh.approx.f32 %0, %1;" : "=f"(y) : "f"(x)); return y;
}
__device__ __forceinline__ float sigt(float x) {
    return fmaf(tanha(0.5f * x), 0.5f, 0.5f);
}
__device__ __forceinline__ float2 ffma2(float2 a, float2 b, float2 c) {
    float2 d;
    asm("fma.rn.f32x2 %0, %1, %2, %3;"
        : "=l"(*reinterpret_cast<unsigned long long*>(&d))
        : "l"(*reinterpret_cast<unsigned long long*>(&a)),
          "l"(*reinterpret_cast<unsigned long long*>(&b)),
          "l"(*reinterpret_cast<unsigned long long*>(&c)));
    return d;
}
__device__ __forceinline__ float2 sp(float x) { return make_float2(x, x); }

// ---------- sort kernels ----------
__global__ void sort_zero() {
    if (threadIdx.x < 32) { g_cnt[threadIdx.x] = 0; g_pos[threadIdx.x] = 0; }
}
__global__ void sort_hist(const int* __restrict__ lens, int N) {
    int i = blockIdx.x * blockDim.x + threadIdx.x;
    if (i < N) {
        int L = lens[i]; if (L < 0) L = 0; if (L > TT) L = TT;
        atomicAdd(&g_cnt[L], 1);
    }
}
__global__ void sort_prefix() {
    if (threadIdx.x == 0) {
        int off = 0;
        for (int L = TT; L >= 0; --L) { g_pos[L] = off; off += g_cnt[L]; }
    }
}
__global__ void sort_scatter(const int* __restrict__ lens, int N) {
    int i = blockIdx.x * blockDim.x + threadIdx.x;
    if (i < N) {
        int L = lens[i]; if (L < 0) L = 0; if (L > TT) L = TT;
        int p = atomicAdd(&g_pos[L], 1);
        g_perm[p] = i;
    }
}

// ---------- fused table builder ----------
__global__ void build_tabs(const float* __restrict__ emb,
                           const float* __restrict__ Wih_f, const float* __restrict__ bih_f,
                           const float* __restrict__ bhh_f,
                           const float* __restrict__ Wih_b, const float* __restrict__ bih_b,
                           const float* __restrict__ bhh_b,
                           const float* __restrict__ Whh_f, const float* __restrict__ Whh_b) {
    int idx = blockIdx.x * blockDim.x + threadIdx.x;
    if (idx < 2 * VV * HH) {
        int dir = idx / (VV * HH);
        int r = idx % (VV * HH);
        int v = r / HH, j = r % HH;
        const float* Wih = dir ? Wih_b : Wih_f;
        const float* bih = dir ? bih_b : bih_f;
        const float* bhh = dir ? bhh_b : bhh_f;
#pragma unroll
        for (int gi = 0; gi < 4; ++gi) {
            int g = gi * HH + j;
            float s = bih[g] + bhh[g];
            if (v != 0) {  // padding_idx 0 -> zero embedding row
                const float* er = emb + v * EE;
                const float* wr = Wih + g * EE;
                float a = 0.f;
#pragma unroll
                for (int e = 0; e < EE; ++e) a += er[e] * wr[e];
                s += a;
            }
            g_xw[dir * VV * G4 + v * G4 + j * 4 + gi] = s;
        }
        return;
    }
    int i2 = idx - 2 * VV * HH;
    if (i2 >= 2 * HH * HH) return;
    int dir = i2 / (HH * HH);
    int r = i2 % (HH * HH);
    int k = r / HH, j = r % HH;
    const float* Whh = dir ? Whh_b : Whh_f;
#pragma unroll
    for (int gi = 0; gi < 4; ++gi)
        g_wt[dir * HH * G4 + k * G4 + j * 4 + gi] = Whh[(gi * HH + j) * HH + k];
}

// ---------- main kernel ----------
// smem floats: sXW[200*204] | sW[50*200] | sH[50*128]
// then bytes:  sCh[20*128] | sPerm int[128] | sLen int[128] | sMax int[4]
#define SMEM_BYTES ((VV * XWS + HH * G4 + HH * NW) * 4 + TT * NW + 128 * 4 + 128 * 4 + 16)

__global__ void __launch_bounds__(NTH, 1)
lstm_main_kernel(const int* __restrict__ chars, const int* __restrict__ lens,
                 float* __restrict__ out, int N) {
    extern __shared__ float smem[];
    float* sXW = smem;                         // VV*XWS
    float* sW  = sXW + VV * XWS;               // HH*G4
    float* sH  = sW + HH * G4;                 // HH*NW
    unsigned char* sCh = (unsigned char*)(sH + HH * NW);       // TT*NW
    int* sPerm = (int*)(sCh + TT * NW);        // NW
    int* sLen  = sPerm + NW;                   // NW
    int* sMax  = sLen + NW;

    const int tid   = threadIdx.x;
    const int dir   = blockIdx.y;
    const int wbase = blockIdx.x * NW;

    // phase 0: permutation for this block
    if (tid < NW) {
        int gi = wbase + tid;
        sPerm[tid] = (gi < N) ? g_perm[gi] : -1;
    }
    if (tid == 0) sMax[0] = (wbase < N) ? lens[g_perm[wbase]] : 0;  // sorted desc -> first is max
    __syncthreads();

    // phase 1: stage tables + per-word data
    const float* gxw = g_xw + dir * VV * G4;
    for (int i = tid; i < VV * G4; i += NTH) {
        int v = i / G4, j = i % G4;
        sXW[v * XWS + j] = gxw[i];
    }
    const float* gwt = g_wt + dir * HH * G4;
    for (int i = tid; i < HH * G4; i += NTH) sW[i] = gwt[i];
    for (int i = tid; i < HH * NW; i += NTH) sH[i] = 0.0f;
    if (tid < NW) {
        int p = sPerm[tid];
        sLen[tid] = (p >= 0) ? lens[p] : 0;
    }
    for (int i = tid; i < NW * TT; i += NTH) {
        int w = i / TT, t = i % TT;
        int p = sPerm[w];
        sCh[t * NW + w] = (unsigned char)((p >= 0) ? chars[p * TT + t] : 0);
    }
    __syncthreads();

    const int blockmax = sMax[0];

    // thread tile: 4 consecutive words x 5 cells
    const int wg = tid & 31, cg = tid >> 5;
    const int w0 = wg * 4, c0 = cg * 5;

    int lenr[4];
#pragma unroll
    for (int j = 0; j < 4; ++j) lenr[j] = sLen[w0 + j];
    int lenmax4 = max(max(lenr[0], lenr[1]), max(lenr[2], lenr[3]));

    float2 cst[2][5];
#pragma unroll
    for (int p = 0; p < 2; ++p)
#pragma unroll
        for (int c = 0; c < 5; ++c) cst[p][c] = make_float2(0.f, 0.f);

    for (int s = 0; s < blockmax; ++s) {
        const bool active = (s < lenmax4);
        float2 acc[2][5][4];
        float4 holdv[5];

        if (active) {
            // per-word char index: fwd = s, bwd = len-1-s (reversed prefix)
            int chv[4];
#pragma unroll
            for (int j = 0; j < 4; ++j) {
                int t_ = dir ? (lenr[j] - 1 - s) : s;
                if (t_ < 0) t_ = 0;
                chv[j] = sCh[t_ * NW + w0 + j];
            }
            // init acc with xw[char]
#pragma unroll
            for (int p = 0; p < 2; ++p) {
                const float4* xa = (const float4*)(sXW + chv[2 * p] * XWS + c0 * 4);
                const float4* xb = (const float4*)(sXW + chv[2 * p + 1] * XWS + c0 * 4);
#pragma unroll
                for (int c = 0; c < 5; ++c) {
                    float4 A = xa[c], B = xb[c];
                    acc[p][c][0] = make_float2(A.x, B.x);
                    acc[p][c][1] = make_float2(A.y, B.y);
                    acc[p][c][2] = make_float2(A.z, B.z);
                    acc[p][c][3] = make_float2(A.w, B.w);
                }
            }
            // recurrent GEMM
#pragma unroll 5
            for (int k = 0; k < HH; ++k) {
                float4 hv = *(const float4*)(sH + k * NW + w0);
                float2 h01 = make_float2(hv.x, hv.y);
                float2 h23 = make_float2(hv.z, hv.w);
                const float4* wr = (const float4*)(sW + k * G4 + c0 * 4);
#pragma unroll
                for (int c = 0; c < 5; ++c) {
                    float4 wv = wr[c];
                    acc[0][c][0] = ffma2(h01, sp(wv.x), acc[0][c][0]);
                    acc[1][c][0] = ffma2(h23, sp(wv.x), acc[1][c][0]);
                    acc[0][c][1] = ffma2(h01, sp(wv.y), acc[0][c][1]);
                    acc[1][c][1] = ffma2(h23, sp(wv.y), acc[1][c][1]);
                    acc[0][c][2] = ffma2(h01, sp(wv.z), acc[0][c][2]);
                    acc[1][c][2] = ffma2(h23, sp(wv.z), acc[1][c][2]);
                    acc[0][c][3] = ffma2(h01, sp(wv.w), acc[0][c][3]);
                    acc[1][c][3] = ffma2(h23, sp(wv.w), acc[1][c][3]);
                }
            }
            // old h (before overwrite)
#pragma unroll
            for (int c = 0; c < 5; ++c)
                holdv[c] = *(const float4*)(sH + (c0 + c) * NW + w0);
        }
        __syncthreads();  // all sH reads done

        if (active) {
#pragma unroll
            for (int c = 0; c < 5; ++c) {
                float hs[4];
                const float* hop = (const float*)&holdv[c];
#pragma unroll
                for (int j = 0; j < 4; ++j) {
                    const int p = j >> 1;
                    float xi, xf, xg, xo, cold;
                    if (j & 1) {
                        xi = acc[p][c][0].y; xf = acc[p][c][1].y;
                        xg = acc[p][c][2].y; xo = acc[p][c][3].y;
                        cold = cst[p][c].y;
                    } else {
                        xi = acc[p][c][0].x; xf = acc[p][c][1].x;
                        xg = acc[p][c][2].x; xo = acc[p][c][3].x;
                        cold = cst[p][c].x;
                    }
                    float cn = sigt(xf) * cold + sigt(xi) * tanha(xg);
                    float hn = sigt(xo) * tanha(cn);
                    bool valid = (s < lenr[j]);
                    float cstore = valid ? cn : cold;
                    if (j & 1) cst[p][c].y = cstore; else cst[p][c].x = cstore;
                    hs[j] = valid ? hn : hop[j];
                }
                *(float4*)(sH + (c0 + c) * NW + w0) = make_float4(hs[0], hs[1], hs[2], hs[3]);
            }
        }
        __syncthreads();  // sH updated
    }

    // output: out[perm[w]][dir*50+k]  (len-0 words keep h=0 -> zeros, correct)
    for (int i = tid; i < HH * NW; i += NTH) {
        int k = i / NW, w = i % NW;
        int p = sPerm[w];
        if (p >= 0) out[(size_t)p * (2 * HH) + dir * HH + k] = sH[k * NW + w];
    }
}

// ---------- launcher ----------
extern "C" void kernel_launch(void* const* d_in, const int* in_sizes, int n_in,
                              void* d_out, int out_size) {
    const int*   chars = (const int*)d_in[0];
    const int*   lens  = (const int*)d_in[1];
    const float* emb   = (const float*)d_in[2];
    const float* Wih_f = (const float*)d_in[3];
    const float* Whh_f = (const float*)d_in[4];
    const float* bih_f = (const float*)d_in[5];
    const float* bhh_f = (const float*)d_in[6];
    const float* Wih_b = (const float*)d_in[7];
    const float* Whh_b = (const float*)d_in[8];
    const float* bih_b = (const float*)d_in[9];
    const float* bhh_b = (const float*)d_in[10];
    float* out = (float*)d_out;

    const int N = in_sizes[1];

    // 1-5: sort + tables (order fixed so ncu -s 5 profiles the main kernel)
    sort_zero<<<1, 32>>>();
    sort_hist<<<(N + 255) / 256, 256>>>(lens, N);
    sort_prefix<<<1, 32>>>();
    sort_scatter<<<(N + 255) / 256, 256>>>(lens, N);
    {
        int total = 2 * VV * HH + 2 * HH * HH;
        build_tabs<<<(total + 127) / 128, 128>>>(emb, Wih_f, bih_f, bhh_f,
                                                 Wih_b, bih_b, bhh_b, Whh_f, Whh_b);
    }

    cudaFuncSetAttribute(lstm_main_kernel,
                         cudaFuncAttributeMaxDynamicSharedMemorySize, SMEM_BYTES);
    dim3 grid((N + NW - 1) / NW, 2);
    lstm_main_kernel<<<grid, NTH, SMEM_BYTES>>>(chars, lens, out, N);
}